// round 1
// baseline (speedup 1.0000x reference)
#include <cuda_runtime.h>
#include <math.h>

// Problem constants
#define NTOT 4
#define CHN  256
#define HSZ  128
#define WSZ  128
#define HWSZ (HSZ*WSZ)          // 16384
#define MTOT (NTOT*HWSZ)        // 65536 pixels
#define GRP  4
#define KTAP 9
#define OMS  112                // PAD_OFF
#define EPSV 1e-5f

// Scratch (static device globals — allocation-free at launch time)
__device__ float g_y [MTOT*CHN];   // silu(bn1(conv1x1(x)))  NHWC
__device__ float g_v [MTOT*CHN];   // value projection       NHWC
__device__ float g_s [MTOT*CHN];   // deformable-sampled     NHWC
__device__ float g_om[MTOT*OMS];   // offsets+masks per pixel

// ---------------------------------------------------------------------------
// Tiled fp32 GEMM: C[p,o] = sum_c A[p,c] * Wt[o,c]  (+ epilogue)
//   ALAYOUT: 0 = A is NHWC (A[p*256+c]); 1 = A is NCHW x input
//   EPI:     0 = +bias, store NHWC
//            1 = bn1+silu (no bias), store NHWC
//            2 = +bias, bn2+silu, store NCHW (final output)
// Block tile: 64 pixels x 64 outputs, k-tile 16, 256 threads, 4x4 per thread.
// ---------------------------------------------------------------------------
template<int ALAYOUT, int EPI>
__global__ __launch_bounds__(256)
void gemm64(const float* __restrict__ A, const float* __restrict__ Wt,
            const float* __restrict__ bias,
            const float* __restrict__ gamma, const float* __restrict__ beta,
            const float* __restrict__ mean,  const float* __restrict__ var,
            float* __restrict__ Co, int Nout, int outStride)
{
    __shared__ float As[16][64];
    __shared__ float Bs[16][64];
    const int tid = threadIdx.x;
    const int tx  = tid & 15;        // output-col group
    const int ty  = tid >> 4;        // pixel-row group
    const int p0  = blockIdx.x * 64;
    const int o0  = blockIdx.y * 64;
    const int nimg = p0 >> 14;       // p0 / HWSZ (tiles never straddle images)
    const int hw0  = p0 & (HWSZ - 1);

    float acc[4][4] = {};

    for (int kt = 0; kt < CHN; kt += 16) {
        // ---- load A tile (16 k x 64 pixels) ----
        if (ALAYOUT == 1) {
            #pragma unroll
            for (int i = 0; i < 4; i++) {
                int e = tid + i * 256;
                int kk = e >> 6, pp = e & 63;
                As[kk][pp] = A[(size_t)nimg * CHN * HWSZ +
                               (size_t)(kt + kk) * HWSZ + hw0 + pp];
            }
        } else {
            int pp = tid >> 2, q = tid & 3;
            float4 t = *reinterpret_cast<const float4*>(
                           &A[(size_t)(p0 + pp) * CHN + kt + q * 4]);
            As[q*4+0][pp] = t.x; As[q*4+1][pp] = t.y;
            As[q*4+2][pp] = t.z; As[q*4+3][pp] = t.w;
        }
        // ---- load B tile (16 k x 64 outputs) ----
        {
            int oo = tid >> 2, q = tid & 3;
            int o  = o0 + oo;
            float4 t = make_float4(0.f, 0.f, 0.f, 0.f);
            if (o < Nout)
                t = *reinterpret_cast<const float4*>(&Wt[(size_t)o * CHN + kt + q * 4]);
            Bs[q*4+0][oo] = t.x; Bs[q*4+1][oo] = t.y;
            Bs[q*4+2][oo] = t.z; Bs[q*4+3][oo] = t.w;
        }
        __syncthreads();
        #pragma unroll
        for (int kk = 0; kk < 16; kk++) {
            float4 av = *reinterpret_cast<const float4*>(&As[kk][ty * 4]);
            float4 bv = *reinterpret_cast<const float4*>(&Bs[kk][tx * 4]);
            float a_[4] = {av.x, av.y, av.z, av.w};
            float b_[4] = {bv.x, bv.y, bv.z, bv.w};
            #pragma unroll
            for (int i = 0; i < 4; i++)
                #pragma unroll
                for (int j = 0; j < 4; j++)
                    acc[i][j] = fmaf(a_[i], b_[j], acc[i][j]);
        }
        __syncthreads();
    }

    // ---- epilogue ----
    #pragma unroll
    for (int j = 0; j < 4; j++) {
        int o = o0 + tx * 4 + j;
        if (o >= Nout) continue;
        float bs = 0.f, sc = 1.f, sh = 0.f;
        if (EPI == 0 || EPI == 2) bs = bias[o];
        if (EPI == 1 || EPI == 2) {
            sc = gamma[o] * rsqrtf(var[o] + EPSV);
            sh = beta[o] - mean[o] * sc;
        }
        #pragma unroll
        for (int i = 0; i < 4; i++) {
            int p = p0 + ty * 4 + i;
            float val = acc[i][j] + bs;
            if (EPI >= 1) {
                val = val * sc + sh;
                val = val / (1.f + expf(-val));   // silu
            }
            if (EPI == 2) {
                Co[((size_t)(p >> 14) * CHN + o) * HWSZ + (p & (HWSZ - 1))] = val;
            } else {
                Co[(size_t)p * outStride + o] = val;
            }
        }
    }
}

// ---------------------------------------------------------------------------
// DCNv4 deformable bilinear sampling.
// One warp per (pixel, group). Each lane owns channels {lane, lane+32} of Cg=64.
// om layout per pixel: 112 floats; group g uses [g*27 .. g*27+26]:
//   2k   -> dw (x offset), 2k+1 -> dh (y offset), 18+k -> mask
// v layout NHWC: v[((n*HW + h*W + w)*256) + g*64 + c]
// ---------------------------------------------------------------------------
__global__ __launch_bounds__(256)
void dcn_sample(const float* __restrict__ v, const float* __restrict__ om,
                float* __restrict__ s)
{
    int warp = (blockIdx.x * 256 + threadIdx.x) >> 5;
    int lane = threadIdx.x & 31;
    int p = warp >> 2;
    int g = warp & 3;
    int n = p >> 14;
    int hw = p & (HWSZ - 1);
    int h = hw >> 7, w = hw & 127;

    const float* op = om + (size_t)p * OMS + g * 27;
    const int cb = g * 64 + lane;
    const int nb = n << 14;          // n * HWSZ

    float acc0 = 0.f, acc1 = 0.f;
    #pragma unroll
    for (int k = 0; k < KTAP; k++) {
        float ow = op[2 * k];        // x offset
        float oh = op[2 * k + 1];    // y offset
        float mk = op[18 + k];       // mask
        float lh = (float)(h + k / 3 - 1) + oh;
        float lw = (float)(w + k % 3 - 1) + ow;
        float fh = floorf(lh), fw = floorf(lw);
        int h0 = (int)fh, w0 = (int)fw;
        float dh = lh - fh, dw = lw - fw;
        float w00 = (1.f - dh) * (1.f - dw) * mk;
        float w01 = (1.f - dh) * dw * mk;
        float w10 = dh * (1.f - dw) * mk;
        float w11 = dh * dw * mk;
        bool hv0 = (h0 >= 0)     && (h0 < HSZ);
        bool hv1 = (h0 + 1 >= 0) && (h0 + 1 < HSZ);
        bool wv0 = (w0 >= 0)     && (w0 < WSZ);
        bool wv1 = (w0 + 1 >= 0) && (w0 + 1 < WSZ);
        int r0 = (nb + h0 * WSZ + w0) << 8;     // *256 channels
        if (hv0 && wv0) { const float* q = v + r0 + cb;
                          acc0 += w00 * q[0]; acc1 += w00 * q[32]; }
        if (hv0 && wv1) { const float* q = v + r0 + 256 + cb;
                          acc0 += w01 * q[0]; acc1 += w01 * q[32]; }
        if (hv1 && wv0) { const float* q = v + r0 + (WSZ << 8) + cb;
                          acc0 += w10 * q[0]; acc1 += w10 * q[32]; }
        if (hv1 && wv1) { const float* q = v + r0 + ((WSZ + 1) << 8) + cb;
                          acc0 += w11 * q[0]; acc1 += w11 * q[32]; }
    }
    size_t ob = (size_t)p * CHN + cb;
    s[ob]      = acc0;
    s[ob + 32] = acc1;
}

// ---------------------------------------------------------------------------
extern "C" void kernel_launch(void* const* d_in, const int* in_sizes, int n_in,
                              void* d_out, int out_size)
{
    const float* x        = (const float*)d_in[0];
    const float* conv_w   = (const float*)d_in[1];   // (C,C,1,1) -> (o,c)
    const float* bn1_g    = (const float*)d_in[2];
    const float* bn1_b    = (const float*)d_in[3];
    const float* bn1_m    = (const float*)d_in[4];
    const float* bn1_v    = (const float*)d_in[5];
    const float* value_w  = (const float*)d_in[6];
    const float* value_b  = (const float*)d_in[7];
    const float* offset_w = (const float*)d_in[8];
    const float* offset_b = (const float*)d_in[9];
    const float* out_w    = (const float*)d_in[10];
    const float* out_b    = (const float*)d_in[11];
    const float* bn2_g    = (const float*)d_in[12];
    const float* bn2_b    = (const float*)d_in[13];
    const float* bn2_m    = (const float*)d_in[14];
    const float* bn2_v    = (const float*)d_in[15];

    float *y, *v, *s, *omp;
    cudaGetSymbolAddress((void**)&y,   g_y);
    cudaGetSymbolAddress((void**)&v,   g_v);
    cudaGetSymbolAddress((void**)&s,   g_s);
    cudaGetSymbolAddress((void**)&omp, g_om);

    dim3 blk(256);
    // 1) y = silu(bn1(conv1x1(x)))   [NCHW in -> NHWC out]
    gemm64<1,1><<<dim3(MTOT/64, CHN/64), blk>>>(
        x, conv_w, nullptr, bn1_g, bn1_b, bn1_m, bn1_v, y, CHN, CHN);
    // 2a) v = y @ value_w^T + value_b
    gemm64<0,0><<<dim3(MTOT/64, CHN/64), blk>>>(
        y, value_w, value_b, nullptr, nullptr, nullptr, nullptr, v, CHN, CHN);
    // 2b) om = y @ offset_w^T + offset_b   (112 outputs)
    gemm64<0,0><<<dim3(MTOT/64, 2), blk>>>(
        y, offset_w, offset_b, nullptr, nullptr, nullptr, nullptr, omp, OMS, OMS);
    // 3) deformable sampling
    dcn_sample<<<(MTOT * GRP) / 8, blk>>>(v, omp, s);
    // 4) out = silu(bn2(s @ out_w^T + out_b))   [NHWC -> NCHW output]
    gemm64<0,2><<<dim3(MTOT/64, CHN/64), blk>>>(
        s, out_w, out_b, bn2_g, bn2_b, bn2_m, bn2_v, (float*)d_out, CHN, CHN);
}

// round 3
// speedup vs baseline: 1.9144x; 1.9144x over previous
#include <cuda_runtime.h>
#include <cuda_bf16.h>
#include <cstdint>
#include <math.h>

// ---------------- problem constants ----------------
#define NTOT 4
#define CHN  256
#define HSZ  128
#define WSZ  128
#define HWSZ 16384
#define MTOT 65536
#define GRP  4
#define KTAP 9
#define OMS  112
#define EPSV 1e-5f

// ---------------- scratch ----------------
__device__ float g_y [MTOT*CHN];
__device__ float g_v [MTOT*CHN];
__device__ float g_s [MTOT*CHN];
__device__ float g_om[MTOT*OMS];

// ---------------- helpers ----------------
__device__ __forceinline__ uint32_t smem_u32(const void* p){
    uint32_t a;
    asm("{ .reg .u64 t; cvta.to.shared.u64 t, %1; cvt.u32.u64 %0, t; }" : "=r"(a) : "l"(p));
    return a;
}
__device__ __forceinline__ void sts128(uint32_t a, uint32_t x, uint32_t y,
                                       uint32_t z, uint32_t w){
    asm volatile("st.shared.v4.b32 [%0], {%1,%2,%3,%4};"
                 :: "r"(a), "r"(x), "r"(y), "r"(z), "r"(w) : "memory");
}
__device__ __forceinline__ void ldsm4(uint32_t& a0, uint32_t& a1, uint32_t& a2,
                                      uint32_t& a3, uint32_t addr){
    asm volatile("ldmatrix.sync.aligned.m8n8.x4.shared.b16 {%0,%1,%2,%3}, [%4];"
                 : "=r"(a0), "=r"(a1), "=r"(a2), "=r"(a3) : "r"(addr));
}
__device__ __forceinline__ void ldsm2(uint32_t& b0, uint32_t& b1, uint32_t addr){
    asm volatile("ldmatrix.sync.aligned.m8n8.x2.shared.b16 {%0,%1}, [%2];"
                 : "=r"(b0), "=r"(b1) : "r"(addr));
}
__device__ __forceinline__ void mma16816(float* c, const uint32_t* a,
                                         const uint32_t* b){
    asm volatile(
        "mma.sync.aligned.m16n8k16.row.col.f32.bf16.bf16.f32 "
        "{%0,%1,%2,%3}, {%4,%5,%6,%7}, {%8,%9}, {%0,%1,%2,%3};"
        : "+f"(c[0]), "+f"(c[1]), "+f"(c[2]), "+f"(c[3])
        : "r"(a[0]), "r"(a[1]), "r"(a[2]), "r"(a[3]), "r"(b[0]), "r"(b[1]));
}
__device__ __forceinline__ uint32_t pack_bf16(float a, float b){
    __nv_bfloat162 h = __floats2bfloat162_rn(a, b);
    return *reinterpret_cast<uint32_t*>(&h);
}
// swizzled byte offset inside a 128x32-bf16 tile: row r (0..127), 16B chunk c (0..3)
__device__ __forceinline__ uint32_t swz(int r, int c){
    return (uint32_t)(r * 64 + ((c ^ ((r >> 1) & 3)) * 16));
}

// ---------------------------------------------------------------------------
// bf16-split tensor-core GEMM: D[p,o] = sum_c A[p,c]*Wt[o,c] + epilogue
//   A fp32; split A = Ah + Al (bf16), W = Wh + Wl; D ~= AhWh + AhWl + AlWh.
//   ALAYOUT: 0 = A NHWC row-contig K; 1 = A is NCHW x (fused transpose)
//   EPI: 0 = +bias NHWC ; 1 = bn+silu NHWC ; 2 = +bias,bn2,silu -> NCHW
// Tile: BM=128, BN=128, BK=32, 8 warps (2x4), warp tile 64x32.
// ---------------------------------------------------------------------------
template<int ALAYOUT, int EPI, int NOUT>
__global__ __launch_bounds__(256)
void gemm_hmma(const float* __restrict__ A, const float* __restrict__ Wt,
               const float* __restrict__ bias,
               const float* __restrict__ gamma, const float* __restrict__ beta,
               const float* __restrict__ mean,  const float* __restrict__ var,
               float* __restrict__ Co)
{
    // smem: 2 stages x (Ahi, Alo, Bhi, Blo) x 8KB = 64KB
    extern __shared__ __align__(16) char dsm[];
    __shared__ float sSC[128], sSH[128];

    const int tid  = threadIdx.x;
    const int wid  = tid >> 5;
    const int lane = tid & 31;
    const int p0   = blockIdx.x * 128;
    const int n0   = blockIdx.y * 128;

    const uint32_t sb = smem_u32(dsm);
    // stage offsets
    auto AHI = [&](int s){ return sb + s * 32768 + 0;     };
    auto ALO = [&](int s){ return sb + s * 32768 + 8192;  };
    auto BHI = [&](int s){ return sb + s * 32768 + 16384; };
    auto BLO = [&](int s){ return sb + s * 32768 + 24576; };

    // epilogue constants for this n-block (val = acc*SC + SH, then silu)
    if (tid < 128) {
        int o = n0 + tid;
        float sc = 1.f, sh = 0.f;
        if (EPI == 0) {
            sh = (o < NOUT) ? bias[o] : 0.f;
        } else if (EPI == 1) {
            float s_ = gamma[o] * rsqrtf(var[o] + EPSV);
            sc = s_; sh = beta[o] - mean[o] * s_;
        } else if (EPI == 2) {
            float s_ = gamma[o] * rsqrtf(var[o] + EPSV);
            sc = s_; sh = (beta[o] - mean[o] * s_) + bias[o] * s_;
        }
        sSC[tid] = sc; sSH[tid] = sh;
    }

    // ---------------- stage loader ----------------
    auto load_stage = [&](int kt, int s) {
        // ---- A tile: rows = pixels, 32 k ----
        if (ALAYOUT == 0) {
            int r  = tid >> 1;
            int cb = (tid & 1) * 2;            // chunks cb, cb+1
            const float* src = A + (size_t)(p0 + r) * 256 + kt + cb * 8;
            float4 f0 = *reinterpret_cast<const float4*>(src);
            float4 f1 = *reinterpret_cast<const float4*>(src + 4);
            float4 f2 = *reinterpret_cast<const float4*>(src + 8);
            float4 f3 = *reinterpret_cast<const float4*>(src + 12);
            float v[16] = {f0.x,f0.y,f0.z,f0.w, f1.x,f1.y,f1.z,f1.w,
                           f2.x,f2.y,f2.z,f2.w, f3.x,f3.y,f3.z,f3.w};
            uint32_t hi[8], lo[8];
            #pragma unroll
            for (int j = 0; j < 8; j++) {
                float a = v[2*j], b = v[2*j+1];
                float ah = __bfloat162float(__float2bfloat16_rn(a));
                float bh = __bfloat162float(__float2bfloat16_rn(b));
                hi[j] = pack_bf16(ah, bh);
                lo[j] = pack_bf16(a - ah, b - bh);
            }
            sts128(AHI(s) + swz(r, cb),   hi[0], hi[1], hi[2], hi[3]);
            sts128(AHI(s) + swz(r, cb+1), hi[4], hi[5], hi[6], hi[7]);
            sts128(ALO(s) + swz(r, cb),   lo[0], lo[1], lo[2], lo[3]);
            sts128(ALO(s) + swz(r, cb+1), lo[4], lo[5], lo[6], lo[7]);
        } else {
            const int nimg = p0 >> 14, hw0 = p0 & 16383;
            const float* xb = A + (size_t)nimg * CHN * HWSZ + hw0;
            int r  = tid & 127;
            int c2 = tid >> 7;                 // 0..1 -> chunks c2*2, c2*2+1
            float v[16];
            #pragma unroll
            for (int j = 0; j < 16; j++)
                v[j] = xb[(size_t)(kt + c2 * 16 + j) * HWSZ + r];
            uint32_t hi[8], lo[8];
            #pragma unroll
            for (int j = 0; j < 8; j++) {
                float a = v[2*j], b = v[2*j+1];
                float ah = __bfloat162float(__float2bfloat16_rn(a));
                float bh = __bfloat162float(__float2bfloat16_rn(b));
                hi[j] = pack_bf16(ah, bh);
                lo[j] = pack_bf16(a - ah, b - bh);
            }
            int cb = c2 * 2;
            sts128(AHI(s) + swz(r, cb),   hi[0], hi[1], hi[2], hi[3]);
            sts128(AHI(s) + swz(r, cb+1), hi[4], hi[5], hi[6], hi[7]);
            sts128(ALO(s) + swz(r, cb),   lo[0], lo[1], lo[2], lo[3]);
            sts128(ALO(s) + swz(r, cb+1), lo[4], lo[5], lo[6], lo[7]);
        }
        // ---- B tile: rows = outputs, 32 k ----
        {
            int r  = tid >> 1;
            int cb = (tid & 1) * 2;
            int o  = n0 + r;
            float v[16];
            if (NOUT == 256 || o < NOUT) {
                const float* src = Wt + (size_t)o * 256 + kt + cb * 8;
                float4 f0 = *reinterpret_cast<const float4*>(src);
                float4 f1 = *reinterpret_cast<const float4*>(src + 4);
                float4 f2 = *reinterpret_cast<const float4*>(src + 8);
                float4 f3 = *reinterpret_cast<const float4*>(src + 12);
                v[0]=f0.x; v[1]=f0.y; v[2]=f0.z; v[3]=f0.w;
                v[4]=f1.x; v[5]=f1.y; v[6]=f1.z; v[7]=f1.w;
                v[8]=f2.x; v[9]=f2.y; v[10]=f2.z; v[11]=f2.w;
                v[12]=f3.x; v[13]=f3.y; v[14]=f3.z; v[15]=f3.w;
            } else {
                #pragma unroll
                for (int j = 0; j < 16; j++) v[j] = 0.f;
            }
            uint32_t hi[8], lo[8];
            #pragma unroll
            for (int j = 0; j < 8; j++) {
                float a = v[2*j], b = v[2*j+1];
                float ah = __bfloat162float(__float2bfloat16_rn(a));
                float bh = __bfloat162float(__float2bfloat16_rn(b));
                hi[j] = pack_bf16(ah, bh);
                lo[j] = pack_bf16(a - ah, b - bh);
            }
            sts128(BHI(s) + swz(r, cb),   hi[0], hi[1], hi[2], hi[3]);
            sts128(BHI(s) + swz(r, cb+1), hi[4], hi[5], hi[6], hi[7]);
            sts128(BLO(s) + swz(r, cb),   lo[0], lo[1], lo[2], lo[3]);
            sts128(BLO(s) + swz(r, cb+1), lo[4], lo[5], lo[6], lo[7]);
        }
    };

    // warp tiling: 2 (M) x 4 (N); warp tile 64x32
    const int wm = (wid >> 2) * 64;        // 0 or 64
    const int wn = (wid & 3) * 32;         // 0,32,64,96

    float acc[4][4][4];                    // [mt][nt][frag]
    #pragma unroll
    for (int i = 0; i < 4; i++)
        #pragma unroll
        for (int j = 0; j < 4; j++)
            #pragma unroll
            for (int q = 0; q < 4; q++) acc[i][j][q] = 0.f;

    load_stage(0, 0);
    __syncthreads();

    #pragma unroll 1
    for (int st = 0; st < 8; st++) {
        const int s = st & 1;
        // issue next-stage global loads after compute? do compute first is fine;
        // simple: compute this stage, then load next, sync.
        #pragma unroll
        for (int kk = 0; kk < 2; kk++) {     // k16 halves of BK=32
            const int c0 = kk * 2;           // chunk base for this k-half
            // fragments
            uint32_t ah[4][4], al[4][4], bh[4][2], bl[4][2];
            #pragma unroll
            for (int mt = 0; mt < 4; mt++) {
                int rr = wm + mt * 16 + (lane & 15);
                int cc = c0 + (lane >> 4);
                uint32_t ad = swz(rr, cc);
                ldsm4(ah[mt][0], ah[mt][1], ah[mt][2], ah[mt][3], AHI(s) + ad);
                ldsm4(al[mt][0], al[mt][1], al[mt][2], al[mt][3], ALO(s) + ad);
            }
            #pragma unroll
            for (int nt = 0; nt < 4; nt++) {
                int rr = wn + nt * 8 + (lane & 7);
                int cc = c0 + ((lane >> 3) & 1);
                uint32_t bd = swz(rr, cc);
                ldsm2(bh[nt][0], bh[nt][1], BHI(s) + bd);
                ldsm2(bl[nt][0], bl[nt][1], BLO(s) + bd);
            }
            #pragma unroll
            for (int mt = 0; mt < 4; mt++)
                #pragma unroll
                for (int nt = 0; nt < 4; nt++) {
                    mma16816(acc[mt][nt], ah[mt], bh[nt]);
                    mma16816(acc[mt][nt], ah[mt], bl[nt]);
                    mma16816(acc[mt][nt], al[mt], bh[nt]);
                }
        }
        if (st < 7) {
            __syncthreads();                 // all reads of buffer s^1 done
            load_stage((st + 1) * 32, s ^ 1);
        }
        __syncthreads();
    }

    // ---------------- epilogue ----------------
    const int qr = lane >> 2;               // 0..7
    const int qc = (lane & 3) * 2;          // 0,2,4,6
    #pragma unroll
    for (int mt = 0; mt < 4; mt++) {
        #pragma unroll
        for (int nt = 0; nt < 4; nt++) {
            int ocl = wn + nt * 8 + qc;      // local col in [0,128)
            int o   = n0 + ocl;
            if (NOUT != 256 && o >= NOUT) continue;
            float sc0 = sSC[ocl],     sh0 = sSH[ocl];
            float sc1 = sSC[ocl + 1], sh1 = sSH[ocl + 1];
            #pragma unroll
            for (int half = 0; half < 2; half++) {
                int p  = p0 + wm + mt * 16 + qr + half * 8;
                float v0 = acc[mt][nt][half * 2 + 0] * sc0 + sh0;
                float v1 = acc[mt][nt][half * 2 + 1] * sc1 + sh1;
                if (EPI >= 1) {
                    v0 = v0 / (1.f + expf(-v0));
                    v1 = v1 / (1.f + expf(-v1));
                }
                if (EPI == 2) {
                    int n = p >> 14, hw = p & 16383;
                    Co[(((size_t)n * 256 + o)     << 14) + hw] = v0;
                    Co[(((size_t)n * 256 + o + 1) << 14) + hw] = v1;
                } else {
                    *reinterpret_cast<float2*>(&Co[(size_t)p * NOUT + o]) =
                        make_float2(v0, v1);
                }
            }
        }
    }
}

// ---------------------------------------------------------------------------
// DCNv4 deformable bilinear sampling (unchanged; next optimization target)
// ---------------------------------------------------------------------------
__global__ __launch_bounds__(256)
void dcn_sample(const float* __restrict__ v, const float* __restrict__ om,
                float* __restrict__ s)
{
    int warp = (blockIdx.x * 256 + threadIdx.x) >> 5;
    int lane = threadIdx.x & 31;
    int p = warp >> 2;
    int g = warp & 3;
    int n = p >> 14;
    int hw = p & (HWSZ - 1);
    int h = hw >> 7, w = hw & 127;

    const float* op = om + (size_t)p * OMS + g * 27;
    const int cb = g * 64 + lane;
    const int nb = n << 14;

    float acc0 = 0.f, acc1 = 0.f;
    #pragma unroll
    for (int k = 0; k < KTAP; k++) {
        float ow = op[2 * k];
        float oh = op[2 * k + 1];
        float mk = op[18 + k];
        float lh = (float)(h + k / 3 - 1) + oh;
        float lw = (float)(w + k % 3 - 1) + ow;
        float fh = floorf(lh), fw = floorf(lw);
        int h0 = (int)fh, w0 = (int)fw;
        float dh = lh - fh, dw = lw - fw;
        float w00 = (1.f - dh) * (1.f - dw) * mk;
        float w01 = (1.f - dh) * dw * mk;
        float w10 = dh * (1.f - dw) * mk;
        float w11 = dh * dw * mk;
        bool hv0 = (h0 >= 0)     && (h0 < HSZ);
        bool hv1 = (h0 + 1 >= 0) && (h0 + 1 < HSZ);
        bool wv0 = (w0 >= 0)     && (w0 < WSZ);
        bool wv1 = (w0 + 1 >= 0) && (w0 + 1 < WSZ);
        int r0 = (nb + h0 * WSZ + w0) << 8;
        if (hv0 && wv0) { const float* q = v + r0 + cb;
                          acc0 += w00 * q[0]; acc1 += w00 * q[32]; }
        if (hv0 && wv1) { const float* q = v + r0 + 256 + cb;
                          acc0 += w01 * q[0]; acc1 += w01 * q[32]; }
        if (hv1 && wv0) { const float* q = v + r0 + (WSZ << 8) + cb;
                          acc0 += w10 * q[0]; acc1 += w10 * q[32]; }
        if (hv1 && wv1) { const float* q = v + r0 + ((WSZ + 1) << 8) + cb;
                          acc0 += w11 * q[0]; acc1 += w11 * q[32]; }
    }
    size_t ob = (size_t)p * CHN + cb;
    s[ob]      = acc0;
    s[ob + 32] = acc1;
}

// ---------------------------------------------------------------------------
extern "C" void kernel_launch(void* const* d_in, const int* in_sizes, int n_in,
                              void* d_out, int out_size)
{
    const float* x        = (const float*)d_in[0];
    const float* conv_w   = (const float*)d_in[1];
    const float* bn1_g    = (const float*)d_in[2];
    const float* bn1_b    = (const float*)d_in[3];
    const float* bn1_m    = (const float*)d_in[4];
    const float* bn1_v    = (const float*)d_in[5];
    const float* value_w  = (const float*)d_in[6];
    const float* value_b  = (const float*)d_in[7];
    const float* offset_w = (const float*)d_in[8];
    const float* offset_b = (const float*)d_in[9];
    const float* out_w    = (const float*)d_in[10];
    const float* out_b    = (const float*)d_in[11];
    const float* bn2_g    = (const float*)d_in[12];
    const float* bn2_b    = (const float*)d_in[13];
    const float* bn2_m    = (const float*)d_in[14];
    const float* bn2_v    = (const float*)d_in[15];

    float *y, *v, *s, *omp;
    cudaGetSymbolAddress((void**)&y,   g_y);
    cudaGetSymbolAddress((void**)&v,   g_v);
    cudaGetSymbolAddress((void**)&s,   g_s);
    cudaGetSymbolAddress((void**)&omp, g_om);

    const int smem = 65536;   // 2 stages x 32KB
    cudaFuncSetAttribute(gemm_hmma<1,1,256>, cudaFuncAttributeMaxDynamicSharedMemorySize, smem);
    cudaFuncSetAttribute(gemm_hmma<0,0,256>, cudaFuncAttributeMaxDynamicSharedMemorySize, smem);
    cudaFuncSetAttribute(gemm_hmma<0,0,112>, cudaFuncAttributeMaxDynamicSharedMemorySize, smem);
    cudaFuncSetAttribute(gemm_hmma<0,2,256>, cudaFuncAttributeMaxDynamicSharedMemorySize, smem);

    const int MT = MTOT / 128;   // 512

    // 1) y = silu(bn1(conv1x1(x)))  [NCHW x -> NHWC y]
    gemm_hmma<1,1,256><<<dim3(MT,2), 256, smem>>>(
        x, conv_w, nullptr, bn1_g, bn1_b, bn1_m, bn1_v, y);
    // 2a) v = y @ value_w^T + value_b
    gemm_hmma<0,0,256><<<dim3(MT,2), 256, smem>>>(
        y, value_w, value_b, nullptr, nullptr, nullptr, nullptr, v);
    // 2b) om = y @ offset_w^T + offset_b (112 outs)
    gemm_hmma<0,0,112><<<dim3(MT,1), 256, smem>>>(
        y, offset_w, offset_b, nullptr, nullptr, nullptr, nullptr, omp);
    // 3) deformable sampling
    dcn_sample<<<(MTOT * GRP) / 8, 256>>>(v, omp, s);
    // 4) out = silu(bn2(s @ out_w^T + out_b))  [NHWC -> NCHW]
    gemm_hmma<0,2,256><<<dim3(MT,2), 256, smem>>>(
        s, out_w, out_b, bn2_g, bn2_b, bn2_m, bn2_v, (float*)d_out);
}

// round 4
// speedup vs baseline: 2.6614x; 1.3902x over previous
#include <cuda_runtime.h>
#include <cuda_bf16.h>
#include <cstdint>
#include <math.h>

// ---------------- problem constants ----------------
#define NTOT 4
#define CHN  256
#define HSZ  128
#define WSZ  128
#define HWSZ 16384
#define MTOT 65536
#define KTAP 9
#define EPSV 1e-5f
#define OMSP 128          // om storage stride (padded from 112)

typedef __nv_bfloat16 bf16;

// ---------------- scratch ----------------
__device__ bf16  g_xhi[MTOT*CHN], g_xlo[MTOT*CHN];   // x transposed+split
__device__ bf16  g_yhi[MTOT*CHN], g_ylo[MTOT*CHN];   // y split
__device__ bf16  g_shi[MTOT*CHN], g_slo[MTOT*CHN];   // sampled split
__device__ float g_v  [MTOT*CHN];                     // value proj fp32
__device__ float g_om [MTOT*OMSP];                    // offsets+masks (pad 128)
__device__ bf16  g_whi[896*CHN],  g_wlo[896*CHN];     // all weights split+padded

// ---------------- helpers ----------------
__device__ __forceinline__ uint32_t smem_u32(const void* p){
    uint32_t a;
    asm("{ .reg .u64 t; cvta.to.shared.u64 t, %1; cvt.u32.u64 %0, t; }" : "=r"(a) : "l"(p));
    return a;
}
__device__ __forceinline__ void cpasync16(uint32_t dst, const void* src){
    asm volatile("cp.async.cg.shared.global [%0], [%1], 16;"
                 :: "r"(dst), "l"(src) : "memory");
}
#define CP_COMMIT()  asm volatile("cp.async.commit_group;" ::: "memory")
#define CP_WAIT(n)   asm volatile("cp.async.wait_group %0;" :: "n"(n) : "memory")

__device__ __forceinline__ void ldsm4(uint32_t& a0, uint32_t& a1, uint32_t& a2,
                                      uint32_t& a3, uint32_t addr){
    asm volatile("ldmatrix.sync.aligned.m8n8.x4.shared.b16 {%0,%1,%2,%3}, [%4];"
                 : "=r"(a0), "=r"(a1), "=r"(a2), "=r"(a3) : "r"(addr));
}
__device__ __forceinline__ void ldsm2(uint32_t& b0, uint32_t& b1, uint32_t addr){
    asm volatile("ldmatrix.sync.aligned.m8n8.x2.shared.b16 {%0,%1}, [%2];"
                 : "=r"(b0), "=r"(b1) : "r"(addr));
}
__device__ __forceinline__ void mma16816(float* c, const uint32_t* a,
                                         const uint32_t* b){
    asm volatile(
        "mma.sync.aligned.m16n8k16.row.col.f32.bf16.bf16.f32 "
        "{%0,%1,%2,%3}, {%4,%5,%6,%7}, {%8,%9}, {%0,%1,%2,%3};"
        : "+f"(c[0]), "+f"(c[1]), "+f"(c[2]), "+f"(c[3])
        : "r"(a[0]), "r"(a[1]), "r"(a[2]), "r"(a[3]), "r"(b[0]), "r"(b[1]));
}
__device__ __forceinline__ uint32_t pack2(bf16 a, bf16 b){
    __nv_bfloat162 h; h.x = a; h.y = b;
    return *reinterpret_cast<uint32_t*>(&h);
}
// swizzled byte offset in a 128-row x 32-bf16 (64B) tile
__device__ __forceinline__ uint32_t swz(int r, int c){
    return (uint32_t)(r * 64 + ((c ^ ((r >> 1) & 3)) * 16));
}

// ---------------------------------------------------------------------------
// Weight split: 896 padded rows x 256 -> hi/lo bf16
//   rows 0-255 conv_w | 256-511 value_w | 512-639 offset_w (112 real) | 640-895 out_w
// ---------------------------------------------------------------------------
__global__ __launch_bounds__(256)
void w_split(const float* __restrict__ conv_w, const float* __restrict__ value_w,
             const float* __restrict__ offset_w, const float* __restrict__ out_w,
             bf16* __restrict__ whi, bf16* __restrict__ wlo)
{
    int idx = blockIdx.x * 256 + threadIdx.x;
    if (idx >= 896 * 256) return;
    int r = idx >> 8, c = idx & 255;
    float v = 0.f;
    if      (r < 256) v = conv_w[r * 256 + c];
    else if (r < 512) v = value_w[(r - 256) * 256 + c];
    else if (r < 640) { int rr = r - 512; if (rr < 112) v = offset_w[rr * 256 + c]; }
    else              v = out_w[(r - 640) * 256 + c];
    bf16 h = __float2bfloat16_rn(v);
    whi[idx] = h;
    wlo[idx] = __float2bfloat16_rn(v - __bfloat162float(h));
}

// ---------------------------------------------------------------------------
// x prepass: NCHW fp32 -> NHWC bf16 hi/lo (transpose + split)
// tile: 32 channels x 128 hw; grid (128 hw-tiles, 8 c-tiles, 4 n)
// ---------------------------------------------------------------------------
__global__ __launch_bounds__(256)
void x_split(const float* __restrict__ x, bf16* __restrict__ xhi,
             bf16* __restrict__ xlo)
{
    __shared__ float t[32][129];
    const int tid = threadIdx.x;
    const int n = blockIdx.z, c0 = blockIdx.y * 32, hw0 = blockIdx.x * 128;
    const float* src = x + ((size_t)n * 256 + c0) * HWSZ + hw0;
    #pragma unroll
    for (int i = 0; i < 16; i++) {
        int e = tid + i * 256;
        int c = e >> 7, p = e & 127;
        t[c][p] = src[(size_t)c * HWSZ + p];
    }
    __syncthreads();
    int p = tid >> 1, half = tid & 1;
    size_t base = ((size_t)n * HWSZ + hw0 + p) * 256 + c0 + half * 16;
    bf16 hi[16], lo[16];
    #pragma unroll
    for (int j = 0; j < 16; j++) {
        float a = t[half * 16 + j][p];
        bf16 h = __float2bfloat16_rn(a);
        hi[j] = h;
        lo[j] = __float2bfloat16_rn(a - __bfloat162float(h));
    }
    *reinterpret_cast<uint4*>(&xhi[base])     = *reinterpret_cast<uint4*>(&hi[0]);
    *reinterpret_cast<uint4*>(&xhi[base + 8]) = *reinterpret_cast<uint4*>(&hi[8]);
    *reinterpret_cast<uint4*>(&xlo[base])     = *reinterpret_cast<uint4*>(&lo[0]);
    *reinterpret_cast<uint4*>(&xlo[base + 8]) = *reinterpret_cast<uint4*>(&lo[8]);
}

// ---------------------------------------------------------------------------
// bf16-split HMMA GEMM, cp.async double-buffered.
//   D[p,o] = sum_c A[p,c]*B[o,c];  A,B pre-split hi/lo bf16, K=256, BK=32.
//   EPI 0: (+SC/SH affine) -> fp32 [p*ostride+o]
//   EPI 1: bn+silu -> bf16 hi/lo split NHWC (y)
//   EPI 2: bias+bn+silu -> fp32 NCHW (final)
// Tile BM=128, BN=128, 8 warps (2x4), warp 64x32.
// ---------------------------------------------------------------------------
template<int EPI>
__global__ __launch_bounds__(256)
void gemm_bf16(const bf16* __restrict__ Ahi, const bf16* __restrict__ Alo,
               const bf16* __restrict__ Bhi, const bf16* __restrict__ Blo,
               const float* __restrict__ bias, int biasN,
               const float* __restrict__ gamma, const float* __restrict__ beta,
               const float* __restrict__ mean,  const float* __restrict__ var,
               float* __restrict__ Co, bf16* __restrict__ CoHi,
               bf16* __restrict__ CoLo, int ostride)
{
    extern __shared__ __align__(16) char dsm[];
    __shared__ float sSC[128], sSH[128];

    const int tid  = threadIdx.x;
    const int wid  = tid >> 5;
    const int lane = tid & 31;
    const int p0   = blockIdx.x * 128;
    const int n0   = blockIdx.y * 128;

    const uint32_t sb = smem_u32(dsm);
    auto AHI = [&](int s){ return sb + s * 32768 + 0;     };
    auto ALO = [&](int s){ return sb + s * 32768 + 8192;  };
    auto BHI = [&](int s){ return sb + s * 32768 + 16384; };
    auto BLO = [&](int s){ return sb + s * 32768 + 24576; };

    if (tid < 128) {
        int o = n0 + tid;
        float sc = 1.f, sh = 0.f;
        if (EPI == 0) {
            sh = (o < biasN) ? bias[o] : 0.f;
        } else if (EPI == 1) {
            float s_ = gamma[o] * rsqrtf(var[o] + EPSV);
            sc = s_; sh = beta[o] - mean[o] * s_;
        } else {
            float s_ = gamma[o] * rsqrtf(var[o] + EPSV);
            sc = s_; sh = (beta[o] - mean[o] * s_) + bias[o] * s_;
        }
        sSC[tid] = sc; sSH[tid] = sh;
    }

    auto load_stage = [&](int kt, int s) {
        #pragma unroll
        for (int i = 0; i < 2; i++) {
            int e = tid + i * 256;            // 0..511
            int r = e >> 2, c = e & 3;
            size_t ao = (size_t)(p0 + r) * 256 + kt + c * 8;
            size_t bo = (size_t)(n0 + r) * 256 + kt + c * 8;
            uint32_t d = swz(r, c);
            cpasync16(AHI(s) + d, Ahi + ao);
            cpasync16(ALO(s) + d, Alo + ao);
            cpasync16(BHI(s) + d, Bhi + bo);
            cpasync16(BLO(s) + d, Blo + bo);
        }
        CP_COMMIT();
    };

    const int wm = (wid >> 2) * 64;
    const int wn = (wid & 3) * 32;

    float acc[4][4][4];
    #pragma unroll
    for (int i = 0; i < 4; i++)
        #pragma unroll
        for (int j = 0; j < 4; j++)
            #pragma unroll
            for (int q = 0; q < 4; q++) acc[i][j][q] = 0.f;

    load_stage(0, 0);

    #pragma unroll 1
    for (int st = 0; st < 8; st++) {
        const int s = st & 1;
        if (st < 7) load_stage((st + 1) * 32, s ^ 1);
        if (st < 7) { CP_WAIT(1); } else { CP_WAIT(0); }
        __syncthreads();

        #pragma unroll
        for (int kk = 0; kk < 2; kk++) {
            const int c0 = kk * 2;
            uint32_t ah[4][4], al[4][4], bh[4][2], bl[4][2];
            #pragma unroll
            for (int mt = 0; mt < 4; mt++) {
                int rr = wm + mt * 16 + (lane & 15);
                int cc = c0 + (lane >> 4);
                uint32_t ad = swz(rr, cc);
                ldsm4(ah[mt][0], ah[mt][1], ah[mt][2], ah[mt][3], AHI(s) + ad);
                ldsm4(al[mt][0], al[mt][1], al[mt][2], al[mt][3], ALO(s) + ad);
            }
            #pragma unroll
            for (int nt = 0; nt < 4; nt++) {
                int rr = wn + nt * 8 + (lane & 7);
                int cc = c0 + ((lane >> 3) & 1);
                uint32_t bd = swz(rr, cc);
                ldsm2(bh[nt][0], bh[nt][1], BHI(s) + bd);
                ldsm2(bl[nt][0], bl[nt][1], BLO(s) + bd);
            }
            #pragma unroll
            for (int mt = 0; mt < 4; mt++)
                #pragma unroll
                for (int nt = 0; nt < 4; nt++) {
                    mma16816(acc[mt][nt], ah[mt], bh[nt]);
                    mma16816(acc[mt][nt], ah[mt], bl[nt]);
                    mma16816(acc[mt][nt], al[mt], bh[nt]);
                }
        }
        __syncthreads();
    }

    // ---------------- epilogue ----------------
    const int qr = lane >> 2;
    const int qc = (lane & 3) * 2;
    #pragma unroll
    for (int mt = 0; mt < 4; mt++) {
        #pragma unroll
        for (int nt = 0; nt < 4; nt++) {
            int ocl = wn + nt * 8 + qc;
            int o   = n0 + ocl;
            float sc0 = sSC[ocl],     sh0 = sSH[ocl];
            float sc1 = sSC[ocl + 1], sh1 = sSH[ocl + 1];
            #pragma unroll
            for (int half = 0; half < 2; half++) {
                int p  = p0 + wm + mt * 16 + qr + half * 8;
                float v0 = acc[mt][nt][half * 2 + 0] * sc0 + sh0;
                float v1 = acc[mt][nt][half * 2 + 1] * sc1 + sh1;
                if (EPI >= 1) {
                    v0 = v0 / (1.f + expf(-v0));
                    v1 = v1 / (1.f + expf(-v1));
                }
                if (EPI == 0) {
                    *reinterpret_cast<float2*>(&Co[(size_t)p * ostride + o]) =
                        make_float2(v0, v1);
                } else if (EPI == 1) {
                    bf16 h0 = __float2bfloat16_rn(v0);
                    bf16 h1 = __float2bfloat16_rn(v1);
                    bf16 l0 = __float2bfloat16_rn(v0 - __bfloat162float(h0));
                    bf16 l1 = __float2bfloat16_rn(v1 - __bfloat162float(h1));
                    size_t ob = (size_t)p * 256 + o;
                    *reinterpret_cast<uint32_t*>(&CoHi[ob]) = pack2(h0, h1);
                    *reinterpret_cast<uint32_t*>(&CoLo[ob]) = pack2(l0, l1);
                } else {
                    int n = p >> 14, hw = p & 16383;
                    Co[(((size_t)n * 256 + o)     << 14) + hw] = v0;
                    Co[(((size_t)n * 256 + o + 1) << 14) + hw] = v1;
                }
            }
        }
    }
}

// ---------------------------------------------------------------------------
// DCNv4 sampling v2: warp = (pixel, 2 groups); lane -> 4 channels via float4.
// om stride 128: group g uses [g*27 .. g*27+26]; writes s as bf16 hi/lo.
// ---------------------------------------------------------------------------
__global__ __launch_bounds__(256)
void dcn_sample(const float* __restrict__ v, const float* __restrict__ om,
                bf16* __restrict__ shi, bf16* __restrict__ slo)
{
    int wrp  = (blockIdx.x * 256 + threadIdx.x) >> 5;
    int lane = threadIdx.x & 31;
    int p = wrp >> 1;
    int g = ((wrp & 1) << 1) + (lane >> 4);
    int laneg = lane & 15;
    int n = p >> 14;
    int hw = p & (HWSZ - 1);
    int h = hw >> 7, w = hw & 127;

    const float* op = om + (size_t)p * OMSP + g * 27;
    const int cb = g * 64 + laneg * 4;
    const int nb = n << 14;

    float a0 = 0.f, a1 = 0.f, a2 = 0.f, a3 = 0.f;
    #pragma unroll
    for (int k = 0; k < KTAP; k++) {
        float ow = op[2 * k];
        float oh = op[2 * k + 1];
        float mk = op[18 + k];
        float lh = (float)(h + k / 3 - 1) + oh;
        float lw = (float)(w + k % 3 - 1) + ow;
        float fh = floorf(lh), fw = floorf(lw);
        int h0 = (int)fh, w0 = (int)fw;
        float dh = lh - fh, dw = lw - fw;
        float w00 = (1.f - dh) * (1.f - dw) * mk;
        float w01 = (1.f - dh) * dw * mk;
        float w10 = dh * (1.f - dw) * mk;
        float w11 = dh * dw * mk;
        bool hv0 = (h0 >= 0)     && (h0 < HSZ);
        bool hv1 = (h0 + 1 >= 0) && (h0 + 1 < HSZ);
        bool wv0 = (w0 >= 0)     && (w0 < WSZ);
        bool wv1 = (w0 + 1 >= 0) && (w0 + 1 < WSZ);
        int r0 = (nb + h0 * WSZ + w0) << 8;
        if (hv0 && wv0) { float4 q = *reinterpret_cast<const float4*>(v + r0 + cb);
                          a0 += w00*q.x; a1 += w00*q.y; a2 += w00*q.z; a3 += w00*q.w; }
        if (hv0 && wv1) { float4 q = *reinterpret_cast<const float4*>(v + r0 + 256 + cb);
                          a0 += w01*q.x; a1 += w01*q.y; a2 += w01*q.z; a3 += w01*q.w; }
        if (hv1 && wv0) { float4 q = *reinterpret_cast<const float4*>(v + r0 + (WSZ << 8) + cb);
                          a0 += w10*q.x; a1 += w10*q.y; a2 += w10*q.z; a3 += w10*q.w; }
        if (hv1 && wv1) { float4 q = *reinterpret_cast<const float4*>(v + r0 + ((WSZ + 1) << 8) + cb);
                          a0 += w11*q.x; a1 += w11*q.y; a2 += w11*q.z; a3 += w11*q.w; }
    }
    // split-store 4 channels
    bf16 h0 = __float2bfloat16_rn(a0), h1 = __float2bfloat16_rn(a1);
    bf16 h2 = __float2bfloat16_rn(a2), h3 = __float2bfloat16_rn(a3);
    uint2 hv, lv;
    hv.x = pack2(h0, h1); hv.y = pack2(h2, h3);
    lv.x = pack2(__float2bfloat16_rn(a0 - __bfloat162float(h0)),
                 __float2bfloat16_rn(a1 - __bfloat162float(h1)));
    lv.y = pack2(__float2bfloat16_rn(a2 - __bfloat162float(h2)),
                 __float2bfloat16_rn(a3 - __bfloat162float(h3)));
    size_t ob = (size_t)p * 256 + cb;
    *reinterpret_cast<uint2*>(&shi[ob]) = hv;
    *reinterpret_cast<uint2*>(&slo[ob]) = lv;
}

// ---------------------------------------------------------------------------
extern "C" void kernel_launch(void* const* d_in, const int* in_sizes, int n_in,
                              void* d_out, int out_size)
{
    const float* x        = (const float*)d_in[0];
    const float* conv_w   = (const float*)d_in[1];
    const float* bn1_g    = (const float*)d_in[2];
    const float* bn1_b    = (const float*)d_in[3];
    const float* bn1_m    = (const float*)d_in[4];
    const float* bn1_v    = (const float*)d_in[5];
    const float* value_w  = (const float*)d_in[6];
    const float* value_b  = (const float*)d_in[7];
    const float* offset_w = (const float*)d_in[8];
    const float* offset_b = (const float*)d_in[9];
    const float* out_w    = (const float*)d_in[10];
    const float* out_b    = (const float*)d_in[11];
    const float* bn2_g    = (const float*)d_in[12];
    const float* bn2_b    = (const float*)d_in[13];
    const float* bn2_m    = (const float*)d_in[14];
    const float* bn2_v    = (const float*)d_in[15];

    bf16 *xhi, *xlo, *yhi, *ylo, *shi, *slo, *whi, *wlo;
    float *v, *omp;
    cudaGetSymbolAddress((void**)&xhi, g_xhi);
    cudaGetSymbolAddress((void**)&xlo, g_xlo);
    cudaGetSymbolAddress((void**)&yhi, g_yhi);
    cudaGetSymbolAddress((void**)&ylo, g_ylo);
    cudaGetSymbolAddress((void**)&shi, g_shi);
    cudaGetSymbolAddress((void**)&slo, g_slo);
    cudaGetSymbolAddress((void**)&whi, g_whi);
    cudaGetSymbolAddress((void**)&wlo, g_wlo);
    cudaGetSymbolAddress((void**)&v,   g_v);
    cudaGetSymbolAddress((void**)&omp, g_om);

    const int smem = 65536;
    cudaFuncSetAttribute(gemm_bf16<0>, cudaFuncAttributeMaxDynamicSharedMemorySize, smem);
    cudaFuncSetAttribute(gemm_bf16<1>, cudaFuncAttributeMaxDynamicSharedMemorySize, smem);
    cudaFuncSetAttribute(gemm_bf16<2>, cudaFuncAttributeMaxDynamicSharedMemorySize, smem);

    // prepasses
    w_split<<<896, 256>>>(conv_w, value_w, offset_w, out_w, whi, wlo);
    x_split<<<dim3(128, 8, 4), 256>>>(x, xhi, xlo);

    const int MT = MTOT / 128;   // 512

    // 1) y = silu(bn1(x @ conv_w^T))        -> y hi/lo
    gemm_bf16<1><<<dim3(MT,2), 256, smem>>>(
        xhi, xlo, whi, wlo, nullptr, 0,
        bn1_g, bn1_b, bn1_m, bn1_v, nullptr, yhi, ylo, 0);
    // 2a) v = y @ value_w^T + value_b       -> fp32 NHWC
    gemm_bf16<0><<<dim3(MT,2), 256, smem>>>(
        yhi, ylo, whi + 256*256, wlo + 256*256, value_b, 256,
        nullptr, nullptr, nullptr, nullptr, v, nullptr, nullptr, 256);
    // 2b) om = y @ offset_w^T + offset_b    -> fp32 stride 128 (112 real)
    gemm_bf16<0><<<dim3(MT,1), 256, smem>>>(
        yhi, ylo, whi + 512*256, wlo + 512*256, offset_b, 112,
        nullptr, nullptr, nullptr, nullptr, omp, nullptr, nullptr, OMSP);
    // 3) deformable sampling -> s hi/lo
    dcn_sample<<<MTOT / 4, 256>>>(v, omp, shi, slo);
    // 4) out = silu(bn2(s @ out_w^T + out_b)) -> NCHW fp32
    gemm_bf16<2><<<dim3(MT,2), 256, smem>>>(
        shi, slo, whi + 640*256, wlo + 640*256, out_b, 256,
        bn2_g, bn2_b, bn2_m, bn2_v, (float*)d_out, nullptr, nullptr, 0);
}

// round 5
// speedup vs baseline: 2.7876x; 1.0474x over previous
#include <cuda_runtime.h>
#include <cuda_bf16.h>
#include <cstdint>
#include <math.h>

// ---------------- problem constants ----------------
#define NTOT 4
#define CHN  256
#define HSZ  128
#define WSZ  128
#define HWSZ 16384
#define MTOT 65536
#define KTAP 9
#define EPSV 1e-5f
#define OMSP 128          // om storage stride (padded from 112)

typedef __nv_bfloat16 bf16;

// ---------------- scratch ----------------
__device__ bf16  g_xhi[MTOT*CHN], g_xlo[MTOT*CHN];   // x transposed+split
__device__ bf16  g_yhi[MTOT*CHN], g_ylo[MTOT*CHN];   // y split
__device__ bf16  g_shi[MTOT*CHN], g_slo[MTOT*CHN];   // sampled split
__device__ float g_v  [MTOT*CHN];                     // value proj fp32
__device__ float g_om [MTOT*OMSP];                    // offsets+masks (pad 128)
__device__ bf16  g_whi[896*CHN],  g_wlo[896*CHN];     // all weights split+padded

// ---------------- helpers ----------------
__device__ __forceinline__ uint32_t smem_u32(const void* p){
    uint32_t a;
    asm("{ .reg .u64 t; cvta.to.shared.u64 t, %1; cvt.u32.u64 %0, t; }" : "=r"(a) : "l"(p));
    return a;
}
__device__ __forceinline__ void cpasync16(uint32_t dst, const void* src){
    asm volatile("cp.async.cg.shared.global [%0], [%1], 16;"
                 :: "r"(dst), "l"(src) : "memory");
}
#define CP_COMMIT()  asm volatile("cp.async.commit_group;" ::: "memory")
#define CP_WAIT(n)   asm volatile("cp.async.wait_group %0;" :: "n"(n) : "memory")

__device__ __forceinline__ void ldsm4(uint32_t& a0, uint32_t& a1, uint32_t& a2,
                                      uint32_t& a3, uint32_t addr){
    asm volatile("ldmatrix.sync.aligned.m8n8.x4.shared.b16 {%0,%1,%2,%3}, [%4];"
                 : "=r"(a0), "=r"(a1), "=r"(a2), "=r"(a3) : "r"(addr));
}
__device__ __forceinline__ void ldsm2(uint32_t& b0, uint32_t& b1, uint32_t addr){
    asm volatile("ldmatrix.sync.aligned.m8n8.x2.shared.b16 {%0,%1}, [%2];"
                 : "=r"(b0), "=r"(b1) : "r"(addr));
}
__device__ __forceinline__ void mma16816(float* c, const uint32_t* a,
                                         const uint32_t* b){
    asm volatile(
        "mma.sync.aligned.m16n8k16.row.col.f32.bf16.bf16.f32 "
        "{%0,%1,%2,%3}, {%4,%5,%6,%7}, {%8,%9}, {%0,%1,%2,%3};"
        : "+f"(c[0]), "+f"(c[1]), "+f"(c[2]), "+f"(c[3])
        : "r"(a[0]), "r"(a[1]), "r"(a[2]), "r"(a[3]), "r"(b[0]), "r"(b[1]));
}
__device__ __forceinline__ uint32_t pack2(bf16 a, bf16 b){
    __nv_bfloat162 h; h.x = a; h.y = b;
    return *reinterpret_cast<uint32_t*>(&h);
}
// swizzled byte offset in a 128-row x 32-bf16 (64B) tile
__device__ __forceinline__ uint32_t swz(int r, int c){
    return (uint32_t)(r * 64 + ((c ^ ((r >> 1) & 3)) * 16));
}

// ---------------------------------------------------------------------------
// Weight split: 896 padded rows x 256 -> hi/lo bf16
//   rows 0-255 conv_w | 256-511 value_w | 512-639 offset_w (112 real) | 640-895 out_w
// ---------------------------------------------------------------------------
__global__ __launch_bounds__(256)
void w_split(const float* __restrict__ conv_w, const float* __restrict__ value_w,
             const float* __restrict__ offset_w, const float* __restrict__ out_w,
             bf16* __restrict__ whi, bf16* __restrict__ wlo)
{
    int idx = blockIdx.x * 256 + threadIdx.x;
    if (idx >= 896 * 256) return;
    int r = idx >> 8, c = idx & 255;
    float v = 0.f;
    if      (r < 256) v = conv_w[r * 256 + c];
    else if (r < 512) v = value_w[(r - 256) * 256 + c];
    else if (r < 640) { int rr = r - 512; if (rr < 112) v = offset_w[rr * 256 + c]; }
    else              v = out_w[(r - 640) * 256 + c];
    bf16 h = __float2bfloat16_rn(v);
    whi[idx] = h;
    wlo[idx] = __float2bfloat16_rn(v - __bfloat162float(h));
}

// ---------------------------------------------------------------------------
// x prepass: NCHW fp32 -> NHWC bf16 hi/lo (transpose + split)
// ---------------------------------------------------------------------------
__global__ __launch_bounds__(256)
void x_split(const float* __restrict__ x, bf16* __restrict__ xhi,
             bf16* __restrict__ xlo)
{
    __shared__ float t[32][129];
    const int tid = threadIdx.x;
    const int n = blockIdx.z, c0 = blockIdx.y * 32, hw0 = blockIdx.x * 128;
    const float* src = x + ((size_t)n * 256 + c0) * HWSZ + hw0;
    #pragma unroll
    for (int i = 0; i < 16; i++) {
        int e = tid + i * 256;
        int c = e >> 7, p = e & 127;
        t[c][p] = src[(size_t)c * HWSZ + p];
    }
    __syncthreads();
    int p = tid >> 1, half = tid & 1;
    size_t base = ((size_t)n * HWSZ + hw0 + p) * 256 + c0 + half * 16;
    bf16 hi[16], lo[16];
    #pragma unroll
    for (int j = 0; j < 16; j++) {
        float a = t[half * 16 + j][p];
        bf16 h = __float2bfloat16_rn(a);
        hi[j] = h;
        lo[j] = __float2bfloat16_rn(a - __bfloat162float(h));
    }
    *reinterpret_cast<uint4*>(&xhi[base])     = *reinterpret_cast<uint4*>(&hi[0]);
    *reinterpret_cast<uint4*>(&xhi[base + 8]) = *reinterpret_cast<uint4*>(&hi[8]);
    *reinterpret_cast<uint4*>(&xlo[base])     = *reinterpret_cast<uint4*>(&lo[0]);
    *reinterpret_cast<uint4*>(&xlo[base + 8]) = *reinterpret_cast<uint4*>(&lo[8]);
}

// ---------------------------------------------------------------------------
// bf16-split HMMA GEMM, 3-stage cp.async pipeline.
//   EPI 0: +bias -> fp32 [p*ostride+o]
//   EPI 1: bn+silu -> bf16 hi/lo NHWC (y)
//   EPI 2: bias+bn+silu -> fp32 NCHW (final)
//   EPI 3: fused v+om: o<256 -> +value_b into Co(v,stride 256);
//          o>=256 -> +offset_b into Co2(om,stride 128)
// Tile BM=128, BN=128, 8 warps (2x4), warp 64x32.
// ---------------------------------------------------------------------------
template<int EPI>
__global__ __launch_bounds__(256, 2)
void gemm_bf16(const bf16* __restrict__ Ahi, const bf16* __restrict__ Alo,
               const bf16* __restrict__ Bhi, const bf16* __restrict__ Blo,
               const float* __restrict__ bias, const float* __restrict__ bias2,
               const float* __restrict__ gamma, const float* __restrict__ beta,
               const float* __restrict__ mean,  const float* __restrict__ var,
               float* __restrict__ Co, float* __restrict__ Co2,
               bf16* __restrict__ CoHi, bf16* __restrict__ CoLo, int ostride)
{
    extern __shared__ __align__(16) char dsm[];
    __shared__ float sSC[128], sSH[128];

    const int tid  = threadIdx.x;
    const int wid  = tid >> 5;
    const int lane = tid & 31;
    const int p0   = blockIdx.x * 128;
    const int n0   = blockIdx.y * 128;

    const uint32_t sb = smem_u32(dsm);
    auto AHI = [&](int s){ return sb + s * 32768 + 0;     };
    auto ALO = [&](int s){ return sb + s * 32768 + 8192;  };
    auto BHI = [&](int s){ return sb + s * 32768 + 16384; };
    auto BLO = [&](int s){ return sb + s * 32768 + 24576; };

    if (tid < 128) {
        int o = n0 + tid;
        float sc = 1.f, sh = 0.f;
        if (EPI == 0) {
            sh = bias[o];
        } else if (EPI == 1) {
            float s_ = gamma[o] * rsqrtf(var[o] + EPSV);
            sc = s_; sh = beta[o] - mean[o] * s_;
        } else if (EPI == 2) {
            float s_ = gamma[o] * rsqrtf(var[o] + EPSV);
            sc = s_; sh = (beta[o] - mean[o] * s_) + bias[o] * s_;
        } else { // EPI 3
            if (o < 256)           sh = bias[o];
            else if (o - 256 < 112) sh = bias2[o - 256];
        }
        sSC[tid] = sc; sSH[tid] = sh;
    }

    auto load_stage = [&](int kt, int s) {
        #pragma unroll
        for (int i = 0; i < 2; i++) {
            int e = tid + i * 256;            // 0..511
            int r = e >> 2, c = e & 3;
            size_t ao = (size_t)(p0 + r) * 256 + kt + c * 8;
            size_t bo = (size_t)(n0 + r) * 256 + kt + c * 8;
            uint32_t d = swz(r, c);
            cpasync16(AHI(s) + d, Ahi + ao);
            cpasync16(ALO(s) + d, Alo + ao);
            cpasync16(BHI(s) + d, Bhi + bo);
            cpasync16(BLO(s) + d, Blo + bo);
        }
        CP_COMMIT();
    };

    const int wm = (wid >> 2) * 64;
    const int wn = (wid & 3) * 32;

    float acc[4][4][4];
    #pragma unroll
    for (int i = 0; i < 4; i++)
        #pragma unroll
        for (int j = 0; j < 4; j++)
            #pragma unroll
            for (int q = 0; q < 4; q++) acc[i][j][q] = 0.f;

    load_stage(0, 0);
    load_stage(32, 1);

    #pragma unroll 1
    for (int st = 0; st < 8; st++) {
        const int s = st % 3;
        if (st == 7) { CP_WAIT(0); } else { CP_WAIT(1); }
        __syncthreads();

        #pragma unroll
        for (int kk = 0; kk < 2; kk++) {
            const int c0 = kk * 2;
            uint32_t ah[4][4], al[4][4], bh[4][2], bl[4][2];
            #pragma unroll
            for (int mt = 0; mt < 4; mt++) {
                int rr = wm + mt * 16 + (lane & 15);
                int cc = c0 + (lane >> 4);
                uint32_t ad = swz(rr, cc);
                ldsm4(ah[mt][0], ah[mt][1], ah[mt][2], ah[mt][3], AHI(s) + ad);
                ldsm4(al[mt][0], al[mt][1], al[mt][2], al[mt][3], ALO(s) + ad);
            }
            #pragma unroll
            for (int nt = 0; nt < 4; nt++) {
                int rr = wn + nt * 8 + (lane & 7);
                int cc = c0 + ((lane >> 3) & 1);
                uint32_t bd = swz(rr, cc);
                ldsm2(bh[nt][0], bh[nt][1], BHI(s) + bd);
                ldsm2(bl[nt][0], bl[nt][1], BLO(s) + bd);
            }
            #pragma unroll
            for (int mt = 0; mt < 4; mt++)
                #pragma unroll
                for (int nt = 0; nt < 4; nt++) {
                    mma16816(acc[mt][nt], ah[mt], bh[nt]);
                    mma16816(acc[mt][nt], ah[mt], bl[nt]);
                    mma16816(acc[mt][nt], al[mt], bh[nt]);
                }
        }
        if (st < 6) load_stage((st + 2) * 32, (st + 2) % 3);
    }

    // ---------------- epilogue ----------------
    const int qr = lane >> 2;
    const int qc = (lane & 3) * 2;
    #pragma unroll
    for (int mt = 0; mt < 4; mt++) {
        #pragma unroll
        for (int nt = 0; nt < 4; nt++) {
            int ocl = wn + nt * 8 + qc;
            int o   = n0 + ocl;
            float sc0 = sSC[ocl],     sh0 = sSH[ocl];
            float sc1 = sSC[ocl + 1], sh1 = sSH[ocl + 1];
            #pragma unroll
            for (int half = 0; half < 2; half++) {
                int p  = p0 + wm + mt * 16 + qr + half * 8;
                float v0 = acc[mt][nt][half * 2 + 0] * sc0 + sh0;
                float v1 = acc[mt][nt][half * 2 + 1] * sc1 + sh1;
                if (EPI == 1 || EPI == 2) {
                    v0 = v0 / (1.f + expf(-v0));
                    v1 = v1 / (1.f + expf(-v1));
                }
                if (EPI == 0) {
                    *reinterpret_cast<float2*>(&Co[(size_t)p * ostride + o]) =
                        make_float2(v0, v1);
                } else if (EPI == 1) {
                    bf16 h0 = __float2bfloat16_rn(v0);
                    bf16 h1 = __float2bfloat16_rn(v1);
                    bf16 l0 = __float2bfloat16_rn(v0 - __bfloat162float(h0));
                    bf16 l1 = __float2bfloat16_rn(v1 - __bfloat162float(h1));
                    size_t ob = (size_t)p * 256 + o;
                    *reinterpret_cast<uint32_t*>(&CoHi[ob]) = pack2(h0, h1);
                    *reinterpret_cast<uint32_t*>(&CoLo[ob]) = pack2(l0, l1);
                } else if (EPI == 2) {
                    int n = p >> 14, hw = p & 16383;
                    Co[(((size_t)n * 256 + o)     << 14) + hw] = v0;
                    Co[(((size_t)n * 256 + o + 1) << 14) + hw] = v1;
                } else { // EPI 3: fused v + om
                    if (o < 256) {
                        *reinterpret_cast<float2*>(&Co[(size_t)p * 256 + o]) =
                            make_float2(v0, v1);
                    } else {
                        *reinterpret_cast<float2*>(&Co2[(size_t)p * OMSP + (o - 256)]) =
                            make_float2(v0, v1);
                    }
                }
            }
        }
    }
}

// ---------------------------------------------------------------------------
// DCNv4 sampling: warp = (pixel, 2 groups); lane -> 4 channels via float4.
// ---------------------------------------------------------------------------
__global__ __launch_bounds__(256)
void dcn_sample(const float* __restrict__ v, const float* __restrict__ om,
                bf16* __restrict__ shi, bf16* __restrict__ slo)
{
    int wrp  = (blockIdx.x * 256 + threadIdx.x) >> 5;
    int lane = threadIdx.x & 31;
    int p = wrp >> 1;
    int g = ((wrp & 1) << 1) + (lane >> 4);
    int laneg = lane & 15;
    int n = p >> 14;
    int hw = p & (HWSZ - 1);
    int h = hw >> 7, w = hw & 127;

    const float* op = om + (size_t)p * OMSP + g * 27;
    const int cb = g * 64 + laneg * 4;
    const int nb = n << 14;

    float a0 = 0.f, a1 = 0.f, a2 = 0.f, a3 = 0.f;
    #pragma unroll
    for (int k = 0; k < KTAP; k++) {
        float ow = op[2 * k];
        float oh = op[2 * k + 1];
        float mk = op[18 + k];
        float lh = (float)(h + k / 3 - 1) + oh;
        float lw = (float)(w + k % 3 - 1) + ow;
        float fh = floorf(lh), fw = floorf(lw);
        int h0 = (int)fh, w0 = (int)fw;
        float dh = lh - fh, dw = lw - fw;
        float w00 = (1.f - dh) * (1.f - dw) * mk;
        float w01 = (1.f - dh) * dw * mk;
        float w10 = dh * (1.f - dw) * mk;
        float w11 = dh * dw * mk;
        bool hv0 = (h0 >= 0)     && (h0 < HSZ);
        bool hv1 = (h0 + 1 >= 0) && (h0 + 1 < HSZ);
        bool wv0 = (w0 >= 0)     && (w0 < WSZ);
        bool wv1 = (w0 + 1 >= 0) && (w0 + 1 < WSZ);
        int r0 = (nb + h0 * WSZ + w0) << 8;
        if (hv0 && wv0) { float4 q = *reinterpret_cast<const float4*>(v + r0 + cb);
                          a0 += w00*q.x; a1 += w00*q.y; a2 += w00*q.z; a3 += w00*q.w; }
        if (hv0 && wv1) { float4 q = *reinterpret_cast<const float4*>(v + r0 + 256 + cb);
                          a0 += w01*q.x; a1 += w01*q.y; a2 += w01*q.z; a3 += w01*q.w; }
        if (hv1 && wv0) { float4 q = *reinterpret_cast<const float4*>(v + r0 + (WSZ << 8) + cb);
                          a0 += w10*q.x; a1 += w10*q.y; a2 += w10*q.z; a3 += w10*q.w; }
        if (hv1 && wv1) { float4 q = *reinterpret_cast<const float4*>(v + r0 + ((WSZ + 1) << 8) + cb);
                          a0 += w11*q.x; a1 += w11*q.y; a2 += w11*q.z; a3 += w11*q.w; }
    }
    bf16 h0 = __float2bfloat16_rn(a0), h1 = __float2bfloat16_rn(a1);
    bf16 h2 = __float2bfloat16_rn(a2), h3 = __float2bfloat16_rn(a3);
    uint2 hv, lv;
    hv.x = pack2(h0, h1); hv.y = pack2(h2, h3);
    lv.x = pack2(__float2bfloat16_rn(a0 - __bfloat162float(h0)),
                 __float2bfloat16_rn(a1 - __bfloat162float(h1)));
    lv.y = pack2(__float2bfloat16_rn(a2 - __bfloat162float(h2)),
                 __float2bfloat16_rn(a3 - __bfloat162float(h3)));
    size_t ob = (size_t)p * 256 + cb;
    *reinterpret_cast<uint2*>(&shi[ob]) = hv;
    *reinterpret_cast<uint2*>(&slo[ob]) = lv;
}

// ---------------------------------------------------------------------------
extern "C" void kernel_launch(void* const* d_in, const int* in_sizes, int n_in,
                              void* d_out, int out_size)
{
    const float* x        = (const float*)d_in[0];
    const float* conv_w   = (const float*)d_in[1];
    const float* bn1_g    = (const float*)d_in[2];
    const float* bn1_b    = (const float*)d_in[3];
    const float* bn1_m    = (const float*)d_in[4];
    const float* bn1_v    = (const float*)d_in[5];
    const float* value_w  = (const float*)d_in[6];
    const float* value_b  = (const float*)d_in[7];
    const float* offset_w = (const float*)d_in[8];
    const float* offset_b = (const float*)d_in[9];
    const float* out_w    = (const float*)d_in[10];
    const float* out_b    = (const float*)d_in[11];
    const float* bn2_g    = (const float*)d_in[12];
    const float* bn2_b    = (const float*)d_in[13];
    const float* bn2_m    = (const float*)d_in[14];
    const float* bn2_v    = (const float*)d_in[15];

    bf16 *xhi, *xlo, *yhi, *ylo, *shi, *slo, *whi, *wlo;
    float *v, *omp;
    cudaGetSymbolAddress((void**)&xhi, g_xhi);
    cudaGetSymbolAddress((void**)&xlo, g_xlo);
    cudaGetSymbolAddress((void**)&yhi, g_yhi);
    cudaGetSymbolAddress((void**)&ylo, g_ylo);
    cudaGetSymbolAddress((void**)&shi, g_shi);
    cudaGetSymbolAddress((void**)&slo, g_slo);
    cudaGetSymbolAddress((void**)&whi, g_whi);
    cudaGetSymbolAddress((void**)&wlo, g_wlo);
    cudaGetSymbolAddress((void**)&v,   g_v);
    cudaGetSymbolAddress((void**)&omp, g_om);

    const int smem = 3 * 32768;   // 96KB, 3 stages
    cudaFuncSetAttribute(gemm_bf16<1>, cudaFuncAttributeMaxDynamicSharedMemorySize, smem);
    cudaFuncSetAttribute(gemm_bf16<2>, cudaFuncAttributeMaxDynamicSharedMemorySize, smem);
    cudaFuncSetAttribute(gemm_bf16<3>, cudaFuncAttributeMaxDynamicSharedMemorySize, smem);

    // prepasses
    w_split<<<896, 256>>>(conv_w, value_w, offset_w, out_w, whi, wlo);
    x_split<<<dim3(128, 8, 4), 256>>>(x, xhi, xlo);

    const int MT = MTOT / 128;   // 512

    // 1) y = silu(bn1(x @ conv_w^T))           -> y hi/lo
    gemm_bf16<1><<<dim3(MT,2), 256, smem>>>(
        xhi, xlo, whi, wlo, nullptr, nullptr,
        bn1_g, bn1_b, bn1_m, bn1_v, nullptr, nullptr, yhi, ylo, 0);
    // 2) fused: v = y@value_w^T + value_b ; om = y@offset_w^T + offset_b
    gemm_bf16<3><<<dim3(MT,3), 256, smem>>>(
        yhi, ylo, whi + 256*256, wlo + 256*256, value_b, offset_b,
        nullptr, nullptr, nullptr, nullptr, v, omp, nullptr, nullptr, 256);
    // 3) deformable sampling -> s hi/lo
    dcn_sample<<<MTOT / 4, 256>>>(v, omp, shi, slo);
    // 4) out = silu(bn2(s @ out_w^T + out_b))  -> NCHW fp32
    gemm_bf16<2><<<dim3(MT,2), 256, smem>>>(
        shi, slo, whi + 640*256, wlo + 640*256, out_b, nullptr,
        bn2_g, bn2_b, bn2_m, bn2_v, (float*)d_out, nullptr, nullptr, nullptr, 0);
}